// round 3
// baseline (speedup 1.0000x reference)
#include <cuda_runtime.h>
#include <cstdint>

// SpikeFP32ScaleBy2K: rows of 32 {0.0,1.0} floats are big-endian FP32 bit
// patterns. out = (k.exp==0 && k.mant==0) ? x : x with exponent replaced by
// (e_x + K) mod 256, where K = two's-complement 8-bit trunc(|k|) derived from
// k's exponent/top-7-mantissa via a 3-level barrel shift (exactly as the
// reference soft-logic circuit does, including the (e_k-127)&7 truncation).
//
// Strategy: warp-per-row. Lane i loads element i (fully coalesced 128B/row),
// ballot packs bits, brev -> standard IEEE layout, integer math, brev back,
// each lane stores its bit as float. 4 rows per warp, loads front-batched.

static constexpr int ROWS_PER_WARP = 4;

__device__ __forceinline__ unsigned row_transform(unsigned Rx, unsigned Rk) {
    // Rx, Rk: IEEE-layout words (bit 31 = sign, 30:23 = exp, 22:0 = mantissa)
    unsigned ek   = (Rk >> 23) & 0xFFu;
    unsigned mk   = Rk & 0x7FFFFFu;
    unsigned val  = 0x80u | (mk >> 16);            // [1, m_k[0..6]] as int
    unsigned shift = (ek - 127u) & 7u;             // only low 3 bits used
    unsigned kabs = val >> (7u - shift);           // barrel shift, zero fill
    unsigned kf   = (Rk & 0x80000000u) ? ((0u - kabs) & 0xFFu) : kabs;
    unsigned enew = (((Rx >> 23) & 0xFFu) + kf) & 0xFFu;
    unsigned scaled = (Rx & 0x807FFFFFu) | (enew << 23);
    bool k_is_zero = (Rk & 0x7FFFFFFFu) == 0u;
    return k_is_zero ? Rx : scaled;
}

__global__ void __launch_bounds__(256)
spike_scale_kernel(const float* __restrict__ x,
                   const float* __restrict__ k,
                   float* __restrict__ out,
                   int nrows) {
    const int lane = threadIdx.x & 31;
    const long long warp_id =
        ((long long)blockIdx.x * blockDim.x + threadIdx.x) >> 5;
    const long long row0 = warp_id * ROWS_PER_WARP;
    if (row0 >= nrows) return;  // warp-uniform exit (all lanes same rows)

    float xv[ROWS_PER_WARP];
    float kv[ROWS_PER_WARP];

    if (row0 + ROWS_PER_WARP <= nrows) {
        // Fast path: front-batch all loads for MLP.
        #pragma unroll
        for (int r = 0; r < ROWS_PER_WARP; r++) {
            long long base = (row0 + r) * 32 + lane;
            xv[r] = x[base];
            kv[r] = k[base];
        }
        unsigned Ro[ROWS_PER_WARP];
        #pragma unroll
        for (int r = 0; r < ROWS_PER_WARP; r++) {
            unsigned Rx = __brev(__ballot_sync(0xFFFFFFFFu, xv[r] != 0.0f));
            unsigned Rk = __brev(__ballot_sync(0xFFFFFFFFu, kv[r] != 0.0f));
            Ro[r] = __brev(row_transform(Rx, Rk));  // back to element order
        }
        #pragma unroll
        for (int r = 0; r < ROWS_PER_WARP; r++) {
            long long base = (row0 + r) * 32 + lane;
            out[base] = (float)((Ro[r] >> lane) & 1u);
        }
    } else {
        // Tail: per-row guard (warp-uniform per row).
        for (int r = 0; r < ROWS_PER_WARP; r++) {
            long long row = row0 + r;
            if (row >= nrows) break;
            long long base = row * 32 + lane;
            unsigned Rx = __brev(__ballot_sync(0xFFFFFFFFu, x[base] != 0.0f));
            unsigned Rk = __brev(__ballot_sync(0xFFFFFFFFu, k[base] != 0.0f));
            unsigned Ro = __brev(row_transform(Rx, Rk));
            out[base] = (float)((Ro >> lane) & 1u);
        }
    }
}

extern "C" void kernel_launch(void* const* d_in, const int* in_sizes, int n_in,
                              void* d_out, int out_size) {
    const float* x = (const float*)d_in[0];
    const float* k = (const float*)d_in[1];
    float* out = (float*)d_out;

    int nrows = in_sizes[0] / 32;

    const int threads = 256;                       // 8 warps/block
    const int rows_per_block = (threads / 32) * ROWS_PER_WARP;  // 32
    int blocks = (nrows + rows_per_block - 1) / rows_per_block;

    spike_scale_kernel<<<blocks, threads>>>(x, k, out, nrows);
}

// round 4
// speedup vs baseline: 1.0524x; 1.0524x over previous
#include <cuda_runtime.h>
#include <cstdint>

// SpikeFP32ScaleBy2K — rows of 32 {0.0,1.0} floats are big-endian FP32 bit
// patterns. out = x with exponent bumped by K = 8-bit two's-complement
// trunc(|k|) (barrel shift of 1.mmmmmmm by 7-((e_k-127)&7)), passthrough
// when k's exp+mantissa bits are all zero. Sign + mantissa always pass
// through unchanged — only elements 1..8 can differ from x.
//
// R3 design: 4 rows per warp-instruction.
//   lane -> (sub = lane>>3: row in group, c = lane&7: float4 chunk)
//   - LDG.128 per lane (8 lanes = one 128B row, fully coalesced)
//   - nibble pack via umin(u,1) (inputs are exactly 0 or 0x3F800000)
//   - 3x shfl_xor OR-butterfly within 8-lane subgroup -> 32-bit row word W
//     (bit e of W = element e of the row)
//   - integer transform runs once per warp-instr for 4 rows at a time
//   - output rebuilt as raw bit patterns (bit * 0x3F800000), STG.128
// 2 groups per warp (8 rows) for front-batched MLP.

static constexpr int GROUPS_PER_WARP = 2;   // 4 rows per group

__device__ __forceinline__ unsigned pack_nib(uint4 u) {
    // each component is 0x00000000 or 0x3F800000 -> umin(.,1) gives the bit
    unsigned a = min(u.x, 1u);
    unsigned b = min(u.y, 1u);
    unsigned c = min(u.z, 1u);
    unsigned d = min(u.w, 1u);
    return a | (b << 1) | (c << 2) | (d << 3);
}

__device__ __forceinline__ unsigned reduce_row(unsigned nib, unsigned s4) {
    unsigned W = nib << s4;                        // bits 4c..4c+3
    W |= __shfl_xor_sync(0xFFFFFFFFu, W, 1);
    W |= __shfl_xor_sync(0xFFFFFFFFu, W, 2);
    W |= __shfl_xor_sync(0xFFFFFFFFu, W, 4);       // stays within 8-lane group
    return W;                                      // element-order row word
}

__device__ __forceinline__ unsigned transform(unsigned Wx, unsigned Wk) {
    // Wx/Wk: element-order words (bit e = element e; elem0=sign,
    // elems 1..8 = exponent MSB..LSB, elems 9..31 = mantissa MSB..LSB)
    unsigned Bk   = __brev(Wk);                    // IEEE layout
    unsigned ek   = (Bk >> 23) & 0xFFu;
    unsigned val  = 0x80u | ((Bk >> 16) & 0x7Fu);  // 1.mmmmmmm
    unsigned sh   = (ek - 127u) & 7u;
    unsigned kabs = val >> (7u - sh);              // zero-fill right shift
    unsigned kf   = (Wk & 1u) ? (0u - kabs) : kabs;  // low 8 bits valid
    unsigned ex   = (__brev(Wx) >> 23) & 0xFFu;
    unsigned enew = ex + kf;                       // mod-256 via mask below
    // Wo bits 1..8 = enew bits 7..0:  (__brev(enew)>>23)&0x1FE does exactly that
    unsigned rev  = (__brev(enew) >> 23) & 0x1FEu;
    unsigned Wo   = (Wx & ~0x1FEu) | rev;          // sign+mantissa passthrough
    bool     kz   = (Wk & ~1u) == 0u;              // exp+mant of k all zero
    return kz ? Wx : Wo;
}

__global__ void __launch_bounds__(256)
spike_scale_kernel(const uint4* __restrict__ x4,
                   const uint4* __restrict__ k4,
                   uint4* __restrict__ out4,
                   int nrows) {
    const int lane = threadIdx.x & 31;
    const int sub  = lane >> 3;        // row within 4-row group
    const int c    = lane & 7;         // float4 chunk within row
    const unsigned s4 = (unsigned)(c * 4);

    const long long warp_id =
        ((long long)blockIdx.x * blockDim.x + threadIdx.x) >> 5;
    const long long row_base = warp_id * (4 * GROUPS_PER_WARP);

    uint4 xv[GROUPS_PER_WARP], kv[GROUPS_PER_WARP];
    long long idx[GROUPS_PER_WARP];
    bool act[GROUPS_PER_WARP];

    // Front-batch all loads (4x LDG.128 in flight per lane).
    #pragma unroll
    for (int g = 0; g < GROUPS_PER_WARP; g++) {
        long long row = row_base + g * 4 + sub;
        act[g] = row < nrows;
        idx[g] = row * 8 + c;
        if (act[g]) {
            xv[g] = x4[idx[g]];
            kv[g] = k4[idx[g]];
        } else {
            xv[g] = make_uint4(0u, 0u, 0u, 0u);
            kv[g] = make_uint4(0u, 0u, 0u, 0u);
        }
    }

    #pragma unroll
    for (int g = 0; g < GROUPS_PER_WARP; g++) {
        unsigned Wx = reduce_row(pack_nib(xv[g]), s4);
        unsigned Wk = reduce_row(pack_nib(kv[g]), s4);
        unsigned Wo = transform(Wx, Wk);

        unsigned t = Wo >> s4;                     // this lane's 4 bits
        uint4 o;
        o.x = (t        & 1u) * 0x3F800000u;       // raw 1.0f / 0.0f bits
        o.y = ((t >> 1) & 1u) * 0x3F800000u;
        o.z = ((t >> 2) & 1u) * 0x3F800000u;
        o.w = ((t >> 3) & 1u) * 0x3F800000u;
        if (act[g]) out4[idx[g]] = o;
    }
}

extern "C" void kernel_launch(void* const* d_in, const int* in_sizes, int n_in,
                              void* d_out, int out_size) {
    const uint4* x4 = (const uint4*)d_in[0];
    const uint4* k4 = (const uint4*)d_in[1];
    uint4* out4 = (uint4*)d_out;

    int nrows = in_sizes[0] / 32;

    const int threads = 256;                                   // 8 warps
    const int rows_per_block = 8 * 4 * GROUPS_PER_WARP;        // 64
    int blocks = (nrows + rows_per_block - 1) / rows_per_block;

    spike_scale_kernel<<<blocks, threads>>>(x4, k4, out4, nrows);
}

// round 5
// speedup vs baseline: 1.0649x; 1.0119x over previous
#include <cuda_runtime.h>
#include <cstdint>

// SpikeFP32ScaleBy2K — rows of 32 {0,1} floats = big-endian FP32 bit pattern.
// out = x with exponent += K (mod 256) where K = 8-bit two's-complement
// trunc-ish(|k|) = (0x80|m_k[0..6]) >> (7 - ((e_k-127)&7)), negated if s_k;
// passthrough when k's exp+mantissa bits are all zero.
// Only elements 1..8 (exponent) ever change; sign+mantissa pass through.
//
// R5: single combined-word OR-butterfly. Each lane (c = lane&7 chunk of 4
// elements, sub = lane>>3 row-in-group) packs exactly the 25 state bits the
// transform needs into disjoint fields using hoisted per-lane shift/mask
// constants; one 3-step shfl_xor OR-reduce per row-group delivers the full
// state to all lanes. 32-bit indexing, LDG.128/STG.128 with .cs hints.
//
// Combined word C layout:
//   [0:8)   e_x value bits  (bit i = x element 8-i)
//   [8:16)  e_k value bits  (bit 8+i = k element 8-i)
//   [16:23) m_k[0..6]       (bit 22-j = k element 9+j)
//   [23]    s_k             (k element 0)
//   [24]    k_nonzero       (OR of k elements 1..31)

static constexpr int GROUPS = 2;                  // 4 rows/group, 8 rows/warp
static constexpr unsigned ONEF = 0x3F800000u;

__device__ __forceinline__ unsigned pack_nib(uint4 u) {
    // components are exactly 0x00000000 or 0x3F800000
    unsigned a = min(u.x, 1u), b = min(u.y, 1u);
    unsigned c = min(u.z, 1u), d = min(u.w, 1u);
    return a | (b << 1) | (c << 2) | (d << 3);
}

__global__ void __launch_bounds__(256)
spike_scale_kernel(const uint4* __restrict__ x4,
                   const uint4* __restrict__ k4,
                   uint4* __restrict__ out4,
                   unsigned nrows) {
    const unsigned lane = threadIdx.x & 31u;
    const unsigned c    = lane & 7u;          // float4 chunk within row
    const unsigned sub  = lane >> 3;          // row within 4-row group
    const unsigned eb   = c * 4u;             // first element index of chunk

    // ── per-lane constants (hoisted out of the group loop) ──
    // exponent-field placement: rev4(nib) bit j (element eb+3-j) -> bit (5-eb)+j
    const unsigned shl = (c <= 1u) ? (5u - eb) : 0u;
    const unsigned shr = (c >= 2u) ? (eb - 5u) : 0u;
    const unsigned Mx  = (c == 0u) ? 0xE0u : (c == 1u) ? 0x1Eu
                       : (c == 2u) ? 0x01u : 0u;
    const unsigned shm = 28u - eb;            // mantissa-field placement
    const unsigned Mkm = (c == 2u) ? 0x700000u : (c == 3u) ? 0xF0000u : 0u;
    const unsigned Msk = (c == 0u) ? 1u : 0u; // sign bit source (element 0)
    const unsigned m0  = (c == 0u) ? 0u : ~0u;// exclude k element0 from knz
    unsigned rmm[4], sho[4];                  // output replace mask + bit pos
    #pragma unroll
    for (int t = 0; t < 4; t++) {
        unsigned e = eb + (unsigned)t;
        bool rep = (e >= 1u && e <= 8u);      // exponent elements only
        rmm[t] = rep ? ~0u : 0u;
        sho[t] = rep ? (8u - e) : 0u;
    }

    const unsigned warp_id = blockIdx.x * (blockDim.x >> 5) + (threadIdx.x >> 5);
    const unsigned row0 = warp_id * (4u * GROUPS);
    if (row0 >= nrows) return;                // warp-uniform

    uint4 xv[GROUPS], kv[GROUPS];
    unsigned idx[GROUPS];
    unsigned safem[GROUPS];                   // ~0 if row valid

    const bool full = (row0 + 4u * GROUPS) <= nrows;

    #pragma unroll
    for (int g = 0; g < GROUPS; g++) {
        unsigned row = row0 + 4u * g + sub;
        unsigned ok  = full | (row < nrows);
        safem[g] = 0u - (unsigned)ok;
        unsigned r = ok ? row : (nrows - 1u); // clamp: keep loads in-bounds
        idx[g] = r * 8u + c;                  // fits 32-bit (max 2^24)
        xv[g] = __ldcs(&x4[idx[g]]);
        kv[g] = __ldcs(&k4[idx[g]]);
    }

    #pragma unroll
    for (int g = 0; g < GROUPS; g++) {
        unsigned nibX = pack_nib(xv[g]);
        unsigned nibK = pack_nib(kv[g]);
        unsigned rX = __brev(nibX) >> 28;     // 4-bit reverse
        unsigned rK = __brev(nibK) >> 28;

        unsigned kOr = (kv[g].x & m0) | kv[g].y | kv[g].z | kv[g].w;
        unsigned C = (((rX << shl) >> shr) & Mx)
                   | ((((rK << shl) >> shr) & Mx) << 8)
                   | ((rK << shm) & Mkm)
                   | ((nibK & Msk) << 23)
                   | (min(kOr, 1u) << 24);

        C |= __shfl_xor_sync(~0u, C, 1);      // OR-butterfly within 8 lanes
        C |= __shfl_xor_sync(~0u, C, 2);
        C |= __shfl_xor_sync(~0u, C, 4);

        // ── the circuit, in integers ──
        unsigned ex   = C & 0xFFu;
        unsigned ek   = (C >> 8) & 0xFFu;
        unsigned val  = 0x80u | ((C >> 16) & 0x7Fu);   // 1.mmmmmmm
        unsigned rs   = (6u - ek) & 7u;                // 7 - ((ek-127)&7)
        unsigned kabs = val >> rs;
        unsigned neg  = 0u - ((C >> 23) & 1u);         // ~0 if s_k
        unsigned kf   = (kabs ^ neg) - neg;            // conditional negate
        unsigned enew = ex + kf;                       // low 8 bits valid
        unsigned knzm = 0u - ((C >> 24) & 1u);         // ~0 if k != 0

        uint4 o;
        {
            unsigned m, b;
            m = rmm[0] & knzm; b = 0u - ((enew >> sho[0]) & 1u);
            o.x = (ONEF & b & m) | (xv[g].x & ~m);
            m = rmm[1] & knzm; b = 0u - ((enew >> sho[1]) & 1u);
            o.y = (ONEF & b & m) | (xv[g].y & ~m);
            m = rmm[2] & knzm; b = 0u - ((enew >> sho[2]) & 1u);
            o.z = (ONEF & b & m) | (xv[g].z & ~m);
            m = rmm[3] & knzm; b = 0u - ((enew >> sho[3]) & 1u);
            o.w = (ONEF & b & m) | (xv[g].w & ~m);
        }
        if (safem[g]) __stcs(&out4[idx[g]], o);
    }
}

extern "C" void kernel_launch(void* const* d_in, const int* in_sizes, int n_in,
                              void* d_out, int out_size) {
    const uint4* x4 = (const uint4*)d_in[0];
    const uint4* k4 = (const uint4*)d_in[1];
    uint4* out4 = (uint4*)d_out;

    unsigned nrows = (unsigned)(in_sizes[0] / 32);

    const int threads = 256;                            // 8 warps
    const int rows_per_block = 8 * 4 * GROUPS;          // 64
    int blocks = (int)((nrows + rows_per_block - 1) / rows_per_block);

    spike_scale_kernel<<<blocks, threads>>>(x4, k4, out4, nrows);
}